// round 3
// baseline (speedup 1.0000x reference)
#include <cuda_runtime.h>
#include <cstdint>

#define Bn 4
#define Cn 16
#define Hn 512
#define Wn 512
#define HWn (Hn*Wn)        // 262144
#define NPIX (Bn*HWn)      // 1048576
#define NOUT (Bn*Cn*HWn)   // 16777216
#define EPSF 1e-10f

// Channel-contiguous accumulator A': layout [pixel][channel]. 64 MB static.
// Zero-initialized at module load; normalize_kernel re-zeros it after reading,
// so every kernel_launch invocation (and every graph replay) starts from 0.
__device__ float g_A[NOUT];
// Weight-sum accumulator D (B,H,W). 4 MB. Same consume-and-rezero protocol.
__device__ float g_D[NPIX];

// vec4 global reduction (sm_90+): one RED message for 4 contiguous floats.
__device__ __forceinline__ void red4(float* addr, float a, float b, float c, float d) {
    asm volatile("red.global.add.v4.f32 [%0], {%1,%2,%3,%4};"
                 :: "l"(addr), "f"(a), "f"(b), "f"(c), "f"(d) : "memory");
}

__device__ __forceinline__ void emit_corner(bool v, float* base, float w,
                                            const float* xv) {
    if (!v) return;
#pragma unroll
    for (int g = 0; g < 4; g++) {
        red4(base + g * 4, xv[4*g+0] * w, xv[4*g+1] * w,
                           xv[4*g+2] * w, xv[4*g+3] * w);
    }
}

// ---------------------------------------------------------------------------
// Kernel 1: scatter. One thread per source pixel. 16 vec4 REDs + 4 scalar.
// x / grid reads use streaming (.cs) loads so they don't evict the
// L2-resident A/D accumulators.
// ---------------------------------------------------------------------------
__global__ void scatter_kernel(const float* __restrict__ x,
                               const float* __restrict__ grid) {
    int p = blockIdx.x * blockDim.x + threadIdx.x;
    if (p >= NPIX) return;

    float2 gv = __ldcs(reinterpret_cast<const float2*>(grid) + p);

    float g0 = (gv.x + 1.0f) * 0.5f;
    float g1 = (gv.y + 1.0f) * 0.5f;
    float gi = fminf(fmaxf(fmaf(g0, 512.0f, 1.0f), 0.0f), 513.0f);
    float gj = fminf(fmaxf(fmaf(g1, 512.0f, 1.0f), 0.0f), 513.0f);

    int ii0 = (int)gi;
    int jj0 = (int)gj;
    float fi = gi - (float)ii0;
    float fj = gj - (float)jj0;
    float wi0 = 1.0f - fi, wi1 = fi;
    float wj0 = 1.0f - fj, wj1 = fj;

    int oi0 = ii0 - 1, oi1 = ii0;
    int oj0 = jj0 - 1, oj1 = jj0;
    bool vi0 = (unsigned)oi0 < (unsigned)Hn;
    bool vi1 = (unsigned)oi1 < (unsigned)Hn;
    bool vj0 = (unsigned)oj0 < (unsigned)Wn;
    bool vj1 = (unsigned)oj1 < (unsigned)Wn;

    bool  v00 = vi0 && vj0,       v01 = vi0 && vj1;
    bool  v10 = vi1 && vj0,       v11 = vi1 && vj1;
    int   o00 = oi0 * Wn + oj0,   o01 = oi0 * Wn + oj1;
    int   o10 = oi1 * Wn + oj0,   o11 = oi1 * Wn + oj1;
    float w00 = wi0 * wj0,        w01 = wi0 * wj1;
    float w10 = wi1 * wj0,        w11 = wi1 * wj1;

    int b   = p >> 18;
    int pix = p & (HWn - 1);

    // D accumulation (4 scalar atomics)
    float* Db = g_D + b * HWn;
    if (v00) atomicAdd(Db + o00, w00);
    if (v01) atomicAdd(Db + o01, w01);
    if (v10) atomicAdd(Db + o10, w10);
    if (v11) atomicAdd(Db + o11, w11);

    // Load the 16 channel values with streaming hint (read-once data)
    const float* xp = x + (size_t)b * Cn * HWn + pix;
    float xv[16];
#pragma unroll
    for (int c = 0; c < Cn; c++) xv[c] = __ldcs(xp + c * HWn);

    // Scatter into channel-contiguous scratch: 4 x vec4 RED per corner
    float* Ab = g_A + (size_t)b * HWn * Cn;
    emit_corner(v00, Ab + (size_t)o00 * Cn, w00, xv);
    emit_corner(v01, Ab + (size_t)o01 * Cn, w01, xv);
    emit_corner(v10, Ab + (size_t)o10 * Cn, w10, xv);
    emit_corner(v11, Ab + (size_t)o11 * Cn, w11, xv);
}

// ---------------------------------------------------------------------------
// Kernel 2: normalize + transpose [pix][c] -> [c][pix], and RE-ZERO the
// scratch it consumed (so the next launch/replay starts from zeros).
// One thread per 4 pixels. Output stores are streaming (.cs).
// ---------------------------------------------------------------------------
__global__ void normalize_kernel(float4* __restrict__ out4) {
    int q = blockIdx.x * blockDim.x + threadIdx.x;
    if (q >= NPIX / 4) return;

    const float4 z = make_float4(0.f, 0.f, 0.f, 0.f);

    float4* D4 = reinterpret_cast<float4*>(g_D);
    float4 d = D4[q];
    D4[q] = z;                     // re-zero D

    float4 r, hf;
    bool bx = d.x > EPSF, by = d.y > EPSF, bz = d.z > EPSF, bw = d.w > EPSF;
    r.x = bx ? 1.0f / (d.x + EPSF) : 0.0f;  hf.x = bx ? 0.0f : 1.0f;
    r.y = by ? 1.0f / (d.y + EPSF) : 0.0f;  hf.y = by ? 0.0f : 1.0f;
    r.z = bz ? 1.0f / (d.z + EPSF) : 0.0f;  hf.z = bz ? 0.0f : 1.0f;
    r.w = bw ? 1.0f / (d.w + EPSF) : 0.0f;  hf.w = bw ? 0.0f : 1.0f;

    int p0  = q * 4;                 // first of 4 consecutive pixels (same batch/row)
    int b   = p0 >> 18;
    int pix = p0 & (HWn - 1);

    float4* A0 = reinterpret_cast<float4*>(g_A + (size_t)p0 * Cn);
    float4* ob = out4 + ((size_t)b * Cn * HWn + pix) / 4;

#pragma unroll
    for (int g = 0; g < 4; g++) {
        float4 a0 = A0[0 * 4 + g];   // pixel p0,   channels 4g..4g+3
        float4 a1 = A0[1 * 4 + g];   // pixel p0+1
        float4 a2 = A0[2 * 4 + g];   // pixel p0+2
        float4 a3 = A0[3 * 4 + g];   // pixel p0+3
        A0[0 * 4 + g] = z;           // re-zero A
        A0[1 * 4 + g] = z;
        A0[2 * 4 + g] = z;
        A0[3 * 4 + g] = z;

        float4 v0 = make_float4(fmaf(a0.x, r.x, hf.x), fmaf(a1.x, r.y, hf.y),
                                fmaf(a2.x, r.z, hf.z), fmaf(a3.x, r.w, hf.w));
        float4 v1 = make_float4(fmaf(a0.y, r.x, hf.x), fmaf(a1.y, r.y, hf.y),
                                fmaf(a2.y, r.z, hf.z), fmaf(a3.y, r.w, hf.w));
        float4 v2 = make_float4(fmaf(a0.z, r.x, hf.x), fmaf(a1.z, r.y, hf.y),
                                fmaf(a2.z, r.z, hf.z), fmaf(a3.z, r.w, hf.w));
        float4 v3 = make_float4(fmaf(a0.w, r.x, hf.x), fmaf(a1.w, r.y, hf.y),
                                fmaf(a2.w, r.z, hf.z), fmaf(a3.w, r.w, hf.w));

        __stcs(&ob[(size_t)(4 * g + 0) * (HWn / 4)], v0);
        __stcs(&ob[(size_t)(4 * g + 1) * (HWn / 4)], v1);
        __stcs(&ob[(size_t)(4 * g + 2) * (HWn / 4)], v2);
        __stcs(&ob[(size_t)(4 * g + 3) * (HWn / 4)], v3);
    }
}

// ---------------------------------------------------------------------------
extern "C" void kernel_launch(void* const* d_in, const int* in_sizes, int n_in,
                              void* d_out, int out_size) {
    const float* x    = (const float*)d_in[0];
    const float* grid = (const float*)d_in[1];
    float*       out  = (float*)d_out;

    scatter_kernel<<<NPIX / 256, 256>>>(x, grid);
    normalize_kernel<<<(NPIX / 4 + 255) / 256, 256>>>((float4*)out);
}

// round 4
// speedup vs baseline: 1.3549x; 1.3549x over previous
#include <cuda_runtime.h>
#include <cstdint>

#define Bn 4
#define Cn 16
#define Hn 512
#define Wn 512
#define HWn (Hn*Wn)        // 262144
#define NPIX (Bn*HWn)      // 1048576
#define NOUT (Bn*Cn*HWn)   // 16777216
#define EPSF 1e-10f

// Channel-contiguous accumulator A': layout [pixel][channel]. 64 MB static.
__device__ float g_A[NOUT];
// Weight-sum accumulator D (B,H,W). 4 MB.
__device__ float g_D[NPIX];

// ---------------------------------------------------------------------------
// Kernel 1: zero scratch A' and D.
// ---------------------------------------------------------------------------
__global__ void zero_kernel() {
    const int n_a4 = NOUT / 4;   // 4194304
    const int n_d4 = NPIX / 4;   // 262144
    int idx = blockIdx.x * blockDim.x + threadIdx.x;
    float4 z = make_float4(0.f, 0.f, 0.f, 0.f);
    if (idx < n_a4) {
        reinterpret_cast<float4*>(g_A)[idx] = z;
    } else if (idx < n_a4 + n_d4) {
        reinterpret_cast<float4*>(g_D)[idx - n_a4] = z;
    }
}

// vec4 global reduction (sm_90+): one RED message for 4 contiguous floats.
__device__ __forceinline__ void red4(float* addr, float a, float b, float c, float d) {
    asm volatile("red.global.add.v4.f32 [%0], {%1,%2,%3,%4};"
                 :: "l"(addr), "f"(a), "f"(b), "f"(c), "f"(d) : "memory");
}

__device__ __forceinline__ void emit_corner(bool v, float* base, float w,
                                            const float* xv) {
    if (!v) return;
#pragma unroll
    for (int g = 0; g < 4; g++) {
        red4(base + g * 4, xv[4*g+0] * w, xv[4*g+1] * w,
                           xv[4*g+2] * w, xv[4*g+3] * w);
    }
}

// ---------------------------------------------------------------------------
// Kernel 2: scatter. One thread per source pixel. 16 vec4 REDs + 4 scalar.
// x / grid reads use streaming (.cs) loads so they don't evict the
// L2-resident A/D accumulators (measured -18us vs plain loads).
// ---------------------------------------------------------------------------
__global__ void scatter_kernel(const float* __restrict__ x,
                               const float* __restrict__ grid) {
    int p = blockIdx.x * blockDim.x + threadIdx.x;
    if (p >= NPIX) return;

    float2 gv = __ldcs(reinterpret_cast<const float2*>(grid) + p);

    float g0 = (gv.x + 1.0f) * 0.5f;
    float g1 = (gv.y + 1.0f) * 0.5f;
    float gi = fminf(fmaxf(fmaf(g0, 512.0f, 1.0f), 0.0f), 513.0f);
    float gj = fminf(fmaxf(fmaf(g1, 512.0f, 1.0f), 0.0f), 513.0f);

    int ii0 = (int)gi;
    int jj0 = (int)gj;
    float fi = gi - (float)ii0;
    float fj = gj - (float)jj0;
    float wi0 = 1.0f - fi, wi1 = fi;
    float wj0 = 1.0f - fj, wj1 = fj;

    int oi0 = ii0 - 1, oi1 = ii0;
    int oj0 = jj0 - 1, oj1 = jj0;
    bool vi0 = (unsigned)oi0 < (unsigned)Hn;
    bool vi1 = (unsigned)oi1 < (unsigned)Hn;
    bool vj0 = (unsigned)oj0 < (unsigned)Wn;
    bool vj1 = (unsigned)oj1 < (unsigned)Wn;

    bool  v00 = vi0 && vj0,       v01 = vi0 && vj1;
    bool  v10 = vi1 && vj0,       v11 = vi1 && vj1;
    int   o00 = oi0 * Wn + oj0,   o01 = oi0 * Wn + oj1;
    int   o10 = oi1 * Wn + oj0,   o11 = oi1 * Wn + oj1;
    float w00 = wi0 * wj0,        w01 = wi0 * wj1;
    float w10 = wi1 * wj0,        w11 = wi1 * wj1;

    int b   = p >> 18;
    int pix = p & (HWn - 1);

    // D accumulation (4 scalar atomics)
    float* Db = g_D + b * HWn;
    if (v00) atomicAdd(Db + o00, w00);
    if (v01) atomicAdd(Db + o01, w01);
    if (v10) atomicAdd(Db + o10, w10);
    if (v11) atomicAdd(Db + o11, w11);

    // Load the 16 channel values with streaming hint (read-once data)
    const float* xp = x + (size_t)b * Cn * HWn + pix;
    float xv[16];
#pragma unroll
    for (int c = 0; c < Cn; c++) xv[c] = __ldcs(xp + c * HWn);

    // Scatter into channel-contiguous scratch: 4 x vec4 RED per corner
    float* Ab = g_A + (size_t)b * HWn * Cn;
    emit_corner(v00, Ab + (size_t)o00 * Cn, w00, xv);
    emit_corner(v01, Ab + (size_t)o01 * Cn, w01, xv);
    emit_corner(v10, Ab + (size_t)o10 * Cn, w10, xv);
    emit_corner(v11, Ab + (size_t)o11 * Cn, w11, xv);
}

// ---------------------------------------------------------------------------
// Kernel 3: normalize + transpose [pix][c] -> [c][pix]. One thread per 4
// pixels. Plain cached loads/stores (R2 configuration: 29us).
// ---------------------------------------------------------------------------
__global__ void normalize_kernel(float4* __restrict__ out4) {
    int q = blockIdx.x * blockDim.x + threadIdx.x;
    if (q >= NPIX / 4) return;

    float4 d = reinterpret_cast<const float4*>(g_D)[q];
    float4 r, hf;
    bool bx = d.x > EPSF, by = d.y > EPSF, bz = d.z > EPSF, bw = d.w > EPSF;
    r.x = bx ? 1.0f / (d.x + EPSF) : 0.0f;  hf.x = bx ? 0.0f : 1.0f;
    r.y = by ? 1.0f / (d.y + EPSF) : 0.0f;  hf.y = by ? 0.0f : 1.0f;
    r.z = bz ? 1.0f / (d.z + EPSF) : 0.0f;  hf.z = bz ? 0.0f : 1.0f;
    r.w = bw ? 1.0f / (d.w + EPSF) : 0.0f;  hf.w = bw ? 0.0f : 1.0f;

    int p0  = q * 4;                 // first of 4 consecutive pixels (same batch/row)
    int b   = p0 >> 18;
    int pix = p0 & (HWn - 1);

    const float4* A0 = reinterpret_cast<const float4*>(g_A + (size_t)p0 * Cn);
    float4* ob = out4 + ((size_t)b * Cn * HWn + pix) / 4;

#pragma unroll
    for (int g = 0; g < 4; g++) {
        float4 a0 = A0[0 * 4 + g];   // pixel p0,   channels 4g..4g+3
        float4 a1 = A0[1 * 4 + g];   // pixel p0+1
        float4 a2 = A0[2 * 4 + g];   // pixel p0+2
        float4 a3 = A0[3 * 4 + g];   // pixel p0+3

        float4 v0 = make_float4(fmaf(a0.x, r.x, hf.x), fmaf(a1.x, r.y, hf.y),
                                fmaf(a2.x, r.z, hf.z), fmaf(a3.x, r.w, hf.w));
        float4 v1 = make_float4(fmaf(a0.y, r.x, hf.x), fmaf(a1.y, r.y, hf.y),
                                fmaf(a2.y, r.z, hf.z), fmaf(a3.y, r.w, hf.w));
        float4 v2 = make_float4(fmaf(a0.z, r.x, hf.x), fmaf(a1.z, r.y, hf.y),
                                fmaf(a2.z, r.z, hf.z), fmaf(a3.z, r.w, hf.w));
        float4 v3 = make_float4(fmaf(a0.w, r.x, hf.x), fmaf(a1.w, r.y, hf.y),
                                fmaf(a2.w, r.z, hf.z), fmaf(a3.w, r.w, hf.w));

        ob[(size_t)(4 * g + 0) * (HWn / 4)] = v0;
        ob[(size_t)(4 * g + 1) * (HWn / 4)] = v1;
        ob[(size_t)(4 * g + 2) * (HWn / 4)] = v2;
        ob[(size_t)(4 * g + 3) * (HWn / 4)] = v3;
    }
}

// ---------------------------------------------------------------------------
extern "C" void kernel_launch(void* const* d_in, const int* in_sizes, int n_in,
                              void* d_out, int out_size) {
    const float* x    = (const float*)d_in[0];
    const float* grid = (const float*)d_in[1];
    float*       out  = (float*)d_out;

    {
        int total = NOUT / 4 + NPIX / 4;
        zero_kernel<<<(total + 255) / 256, 256>>>();
    }
    scatter_kernel<<<NPIX / 256, 256>>>(x, grid);
    normalize_kernel<<<(NPIX / 4 + 255) / 256, 256>>>((float4*)out);
}

// round 5
// speedup vs baseline: 1.6392x; 1.2099x over previous
#include <cuda_runtime.h>
#include <cuda_fp16.h>
#include <cstdint>

#define Bn 4
#define Cn 16
#define Hn 512
#define Wn 512
#define HWn (Hn*Wn)        // 262144
#define NPIX (Bn*HWn)      // 1048576
#define NOUT (Bn*Cn*HWn)   // 16777216
#define EPSF 1e-10f

// Channel-contiguous f16 accumulator A': layout [pixel][16 x half] = 32B/record.
// 32 MB static scratch. Per corner: 2 x 16B vec4.f16x2 RED messages.
__device__ __half2 g_Ah[NOUT / 2];
// Weight-sum accumulator D (B,H,W), kept in f32 for exact hole detection. 4 MB.
__device__ float g_D[NPIX];

// ---------------------------------------------------------------------------
// Kernel 1: zero scratch A' and D. (36 MB, ~7us streaming)
// ---------------------------------------------------------------------------
__global__ void zero_kernel() {
    const int n_a4 = (NOUT * 2) / 16;   // 2097152 float4-units of A (32MB)
    const int n_d4 = NPIX / 4;          // 262144
    int idx = blockIdx.x * blockDim.x + threadIdx.x;
    float4 z = make_float4(0.f, 0.f, 0.f, 0.f);
    if (idx < n_a4) {
        reinterpret_cast<float4*>(g_Ah)[idx] = z;
    } else if (idx < n_a4 + n_d4) {
        reinterpret_cast<float4*>(g_D)[idx - n_a4] = z;
    }
}

// ---------------------------------------------------------------------------
// f16 corner emission: 16 channels * w -> 8 x f16x2 -> 2 x 16B RED messages.
// Products computed in f32; single f16 rounding per contribution.
// ---------------------------------------------------------------------------
__device__ __forceinline__ void emit_corner_h(bool v, __half2* base, float w,
                                              const float* xv) {
    if (!v) return;
    uint32_t m[8];
#pragma unroll
    for (int k = 0; k < 8; k++) {
        __half2 h = __floats2half2_rn(xv[2 * k] * w, xv[2 * k + 1] * w);
        m[k] = *reinterpret_cast<uint32_t*>(&h);
    }
    asm volatile("red.global.add.noftz.v4.f16x2 [%0], {%1,%2,%3,%4};"
                 :: "l"(base), "r"(m[0]), "r"(m[1]), "r"(m[2]), "r"(m[3]) : "memory");
    asm volatile("red.global.add.noftz.v4.f16x2 [%0], {%1,%2,%3,%4};"
                 :: "l"(base + 4), "r"(m[4]), "r"(m[5]), "r"(m[6]), "r"(m[7]) : "memory");
}

// ---------------------------------------------------------------------------
// Kernel 2: scatter. One thread per source pixel. 8 vec f16x2 REDs + 4 scalar
// f32 REDs = 12 LSU lane-messages per pixel (vs 20 in the f32 version).
// ---------------------------------------------------------------------------
__global__ void scatter_kernel(const float* __restrict__ x,
                               const float* __restrict__ grid) {
    int p = blockIdx.x * blockDim.x + threadIdx.x;
    if (p >= NPIX) return;

    float2 gv = __ldcs(reinterpret_cast<const float2*>(grid) + p);

    float g0 = (gv.x + 1.0f) * 0.5f;
    float g1 = (gv.y + 1.0f) * 0.5f;
    float gi = fminf(fmaxf(fmaf(g0, 512.0f, 1.0f), 0.0f), 513.0f);
    float gj = fminf(fmaxf(fmaf(g1, 512.0f, 1.0f), 0.0f), 513.0f);

    int ii0 = (int)gi;
    int jj0 = (int)gj;
    float fi = gi - (float)ii0;
    float fj = gj - (float)jj0;
    float wi0 = 1.0f - fi, wi1 = fi;
    float wj0 = 1.0f - fj, wj1 = fj;

    int oi0 = ii0 - 1, oi1 = ii0;
    int oj0 = jj0 - 1, oj1 = jj0;
    bool vi0 = (unsigned)oi0 < (unsigned)Hn;
    bool vi1 = (unsigned)oi1 < (unsigned)Hn;
    bool vj0 = (unsigned)oj0 < (unsigned)Wn;
    bool vj1 = (unsigned)oj1 < (unsigned)Wn;

    bool  v00 = vi0 && vj0,       v01 = vi0 && vj1;
    bool  v10 = vi1 && vj0,       v11 = vi1 && vj1;
    int   o00 = oi0 * Wn + oj0,   o01 = oi0 * Wn + oj1;
    int   o10 = oi1 * Wn + oj0,   o11 = oi1 * Wn + oj1;
    float w00 = wi0 * wj0,        w01 = wi0 * wj1;
    float w10 = wi1 * wj0,        w11 = wi1 * wj1;

    int b   = p >> 18;
    int pix = p & (HWn - 1);

    // D accumulation (4 scalar f32 atomics; exactness preserved)
    float* Db = g_D + b * HWn;
    if (v00) atomicAdd(Db + o00, w00);
    if (v01) atomicAdd(Db + o01, w01);
    if (v10) atomicAdd(Db + o10, w10);
    if (v11) atomicAdd(Db + o11, w11);

    // Load the 16 channel values with streaming hint (read-once data)
    const float* xp = x + (size_t)b * Cn * HWn + pix;
    float xv[16];
#pragma unroll
    for (int c = 0; c < Cn; c++) xv[c] = __ldcs(xp + c * HWn);

    // Scatter into f16 channel-contiguous scratch: 2 x 16B RED per corner
    __half2* Ab = g_Ah + (size_t)b * HWn * 8;   // 8 half2 per pixel record
    emit_corner_h(v00, Ab + (size_t)o00 * 8, w00, xv);
    emit_corner_h(v01, Ab + (size_t)o01 * 8, w01, xv);
    emit_corner_h(v10, Ab + (size_t)o10 * 8, w10, xv);
    emit_corner_h(v11, Ab + (size_t)o11 * 8, w11, xv);
}

// ---------------------------------------------------------------------------
// Kernel 3: normalize + transpose [pix][c](f16) -> [c][pix](f32).
// One thread per 4 consecutive pixels (same batch/row). Fully coalesced.
// ---------------------------------------------------------------------------
__global__ void normalize_kernel(float4* __restrict__ out4) {
    int q = blockIdx.x * blockDim.x + threadIdx.x;
    if (q >= NPIX / 4) return;

    float4 d = reinterpret_cast<const float4*>(g_D)[q];
    float4 r, hf;
    bool bx = d.x > EPSF, by = d.y > EPSF, bz = d.z > EPSF, bw = d.w > EPSF;
    r.x = bx ? 1.0f / (d.x + EPSF) : 0.0f;  hf.x = bx ? 0.0f : 1.0f;
    r.y = by ? 1.0f / (d.y + EPSF) : 0.0f;  hf.y = by ? 0.0f : 1.0f;
    r.z = bz ? 1.0f / (d.z + EPSF) : 0.0f;  hf.z = bz ? 0.0f : 1.0f;
    r.w = bw ? 1.0f / (d.w + EPSF) : 0.0f;  hf.w = bw ? 0.0f : 1.0f;

    int p0  = q * 4;
    int b   = p0 >> 18;
    int pix = p0 & (HWn - 1);

    // Each pixel record = 2 x uint4 (16 halves). Load all 4 pixels' records.
    const uint4* A4 = reinterpret_cast<const uint4*>(g_Ah);
    uint4 u[4][2];
#pragma unroll
    for (int t = 0; t < 4; t++) {
        u[t][0] = A4[(size_t)(p0 + t) * 2 + 0];   // channels 0..7
        u[t][1] = A4[(size_t)(p0 + t) * 2 + 1];   // channels 8..15
    }

    float4* ob = out4 + ((size_t)b * Cn * HWn + pix) / 4;

#pragma unroll
    for (int g = 0; g < 4; g++) {
        // half2 words for channels 4g..4g+3 of each pixel
        float2 lo[4], hi[4];
#pragma unroll
        for (int t = 0; t < 4; t++) {
            const uint32_t* w32 = reinterpret_cast<const uint32_t*>(&u[t][g >> 1]);
            uint32_t wlo = w32[(g & 1) * 2 + 0];
            uint32_t whi = w32[(g & 1) * 2 + 1];
            lo[t] = __half22float2(*reinterpret_cast<const __half2*>(&wlo));
            hi[t] = __half22float2(*reinterpret_cast<const __half2*>(&whi));
        }

        float4 v0 = make_float4(fmaf(lo[0].x, r.x, hf.x), fmaf(lo[1].x, r.y, hf.y),
                                fmaf(lo[2].x, r.z, hf.z), fmaf(lo[3].x, r.w, hf.w));
        float4 v1 = make_float4(fmaf(lo[0].y, r.x, hf.x), fmaf(lo[1].y, r.y, hf.y),
                                fmaf(lo[2].y, r.z, hf.z), fmaf(lo[3].y, r.w, hf.w));
        float4 v2 = make_float4(fmaf(hi[0].x, r.x, hf.x), fmaf(hi[1].x, r.y, hf.y),
                                fmaf(hi[2].x, r.z, hf.z), fmaf(hi[3].x, r.w, hf.w));
        float4 v3 = make_float4(fmaf(hi[0].y, r.x, hf.x), fmaf(hi[1].y, r.y, hf.y),
                                fmaf(hi[2].y, r.z, hf.z), fmaf(hi[3].y, r.w, hf.w));

        ob[(size_t)(4 * g + 0) * (HWn / 4)] = v0;
        ob[(size_t)(4 * g + 1) * (HWn / 4)] = v1;
        ob[(size_t)(4 * g + 2) * (HWn / 4)] = v2;
        ob[(size_t)(4 * g + 3) * (HWn / 4)] = v3;
    }
}

// ---------------------------------------------------------------------------
extern "C" void kernel_launch(void* const* d_in, const int* in_sizes, int n_in,
                              void* d_out, int out_size) {
    const float* x    = (const float*)d_in[0];
    const float* grid = (const float*)d_in[1];
    float*       out  = (float*)d_out;

    {
        int total = (NOUT * 2) / 16 + NPIX / 4;
        zero_kernel<<<(total + 255) / 256, 256>>>();
    }
    scatter_kernel<<<NPIX / 256, 256>>>(x, grid);
    normalize_kernel<<<(NPIX / 4 + 255) / 256, 256>>>((float4*)out);
}

// round 6
// speedup vs baseline: 2.2774x; 1.3894x over previous
#include <cuda_runtime.h>
#include <cuda_fp16.h>
#include <cstdint>

#define Bn 4
#define Cn 16
#define Hn 512
#define Wn 512
#define HWn (Hn*Wn)        // 262144
#define NPIX (Bn*HWn)      // 1048576
#define NOUT (Bn*Cn*HWn)   // 16777216
#define EPSF 1e-10f

// Channel-contiguous f16 accumulator A': [pixel][16 x half] = 32B/record. 32 MB.
__device__ __half2 g_Ah[NOUT / 2];
// Weight-sum accumulator D (B,H,W), f32 for exact hole detection. 4 MB.
__device__ float g_D[NPIX];

// ---------------------------------------------------------------------------
// Kernel 1: zero scratch A' and D.
// ---------------------------------------------------------------------------
__global__ void zero_kernel() {
    const int n_a4 = (NOUT * 2) / 16;   // 2097152 float4-units of A (32MB)
    const int n_d4 = NPIX / 4;          // 262144
    int idx = blockIdx.x * blockDim.x + threadIdx.x;
    float4 z = make_float4(0.f, 0.f, 0.f, 0.f);
    if (idx < n_a4) {
        reinterpret_cast<float4*>(g_Ah)[idx] = z;
    } else if (idx < n_a4 + n_d4) {
        reinterpret_cast<float4*>(g_D)[idx - n_a4] = z;
    }
}

// ---------------------------------------------------------------------------
// f16 corner emission: 8 HMUL2 against broadcast weight -> 2 x 16B REDs.
// ---------------------------------------------------------------------------
__device__ __forceinline__ void emit_corner_h(bool v, __half2* base, float w,
                                              const uint32_t* xh) {
    if (!v) return;
    __half2 wh = __float2half2_rn(w);
    uint32_t m[8];
#pragma unroll
    for (int k = 0; k < 8; k++) {
        __half2 prod = __hmul2(*reinterpret_cast<const __half2*>(&xh[k]), wh);
        m[k] = *reinterpret_cast<uint32_t*>(&prod);
    }
    asm volatile("red.global.add.noftz.v4.f16x2 [%0], {%1,%2,%3,%4};"
                 :: "l"(base), "r"(m[0]), "r"(m[1]), "r"(m[2]), "r"(m[3]) : "memory");
    asm volatile("red.global.add.noftz.v4.f16x2 [%0], {%1,%2,%3,%4};"
                 :: "l"(base + 4), "r"(m[4]), "r"(m[5]), "r"(m[6]), "r"(m[7]) : "memory");
}

__device__ __forceinline__ void red2(float* addr, float a, float b) {
    asm volatile("red.global.add.v2.f32 [%0], {%1,%2};"
                 :: "l"(addr), "f"(a), "f"(b) : "memory");
}

// ---------------------------------------------------------------------------
// Kernel 2: scatter. One thread per source pixel.
// 8 f16x2-vec4 REDs + ~3 f32 D REDs = ~11 LSU lane-messages per pixel.
// ---------------------------------------------------------------------------
__global__ void scatter_kernel(const float* __restrict__ x,
                               const float* __restrict__ grid) {
    int p = blockIdx.x * blockDim.x + threadIdx.x;
    if (p >= NPIX) return;

    float2 gv = __ldcs(reinterpret_cast<const float2*>(grid) + p);

    float g0 = (gv.x + 1.0f) * 0.5f;
    float g1 = (gv.y + 1.0f) * 0.5f;
    float gi = fminf(fmaxf(fmaf(g0, 512.0f, 1.0f), 0.0f), 513.0f);
    float gj = fminf(fmaxf(fmaf(g1, 512.0f, 1.0f), 0.0f), 513.0f);

    int ii0 = (int)gi;
    int jj0 = (int)gj;
    float fi = gi - (float)ii0;
    float fj = gj - (float)jj0;
    float wi0 = 1.0f - fi, wi1 = fi;
    float wj0 = 1.0f - fj, wj1 = fj;

    int oi0 = ii0 - 1, oi1 = ii0;
    int oj0 = jj0 - 1, oj1 = jj0;
    bool vi0 = (unsigned)oi0 < (unsigned)Hn;
    bool vi1 = (unsigned)oi1 < (unsigned)Hn;
    bool vj0 = (unsigned)oj0 < (unsigned)Wn;
    bool vj1 = (unsigned)oj1 < (unsigned)Wn;

    bool  v00 = vi0 && vj0,       v01 = vi0 && vj1;
    bool  v10 = vi1 && vj0,       v11 = vi1 && vj1;
    int   o00 = oi0 * Wn + oj0,   o01 = oi0 * Wn + oj1;
    int   o10 = oi1 * Wn + oj0,   o11 = oi1 * Wn + oj1;
    float w00 = wi0 * wj0,        w01 = wi0 * wj1;
    float w10 = wi1 * wj0,        w11 = wi1 * wj1;

    int b   = p >> 18;
    int pix = p & (HWn - 1);

    // D accumulation: pair adjacent columns into one v2 RED when 8B-aligned.
    // o00 parity == oj0 parity (row stride 512 is even). oj0=-1 -> odd -> scalar.
    float* Db = g_D + b * HWn;
    bool even = ((oj0 & 1) == 0);
    if (v00 && v01 && even) {
        red2(Db + o00, w00, w01);
    } else {
        if (v00) atomicAdd(Db + o00, w00);
        if (v01) atomicAdd(Db + o01, w01);
    }
    if (v10 && v11 && even) {
        red2(Db + o10, w10, w11);
    } else {
        if (v10) atomicAdd(Db + o10, w10);
        if (v11) atomicAdd(Db + o11, w11);
    }

    // Load the 16 channel values (streaming) and convert to f16x2 ONCE.
    const float* xp = x + (size_t)b * Cn * HWn + pix;
    float xv[16];
#pragma unroll
    for (int c = 0; c < Cn; c++) xv[c] = __ldcs(xp + c * HWn);
    uint32_t xh[8];
#pragma unroll
    for (int k = 0; k < 8; k++) {
        __half2 h = __floats2half2_rn(xv[2 * k], xv[2 * k + 1]);
        xh[k] = *reinterpret_cast<uint32_t*>(&h);
    }

    // Scatter into f16 channel-contiguous scratch: 2 x 16B RED per corner
    __half2* Ab = g_Ah + (size_t)b * HWn * 8;   // 8 half2 per pixel record
    emit_corner_h(v00, Ab + (size_t)o00 * 8, w00, xh);
    emit_corner_h(v01, Ab + (size_t)o01 * 8, w01, xh);
    emit_corner_h(v10, Ab + (size_t)o10 * 8, w10, xh);
    emit_corner_h(v11, Ab + (size_t)o11 * 8, w11, xh);
}

// ---------------------------------------------------------------------------
// Kernel 3: normalize + transpose [pix][c](f16) -> [c][pix](f32).
// One thread per 4 consecutive pixels. Fully coalesced.
// ---------------------------------------------------------------------------
__global__ void normalize_kernel(float4* __restrict__ out4) {
    int q = blockIdx.x * blockDim.x + threadIdx.x;
    if (q >= NPIX / 4) return;

    float4 d = reinterpret_cast<const float4*>(g_D)[q];
    float4 r, hf;
    bool bx = d.x > EPSF, by = d.y > EPSF, bz = d.z > EPSF, bw = d.w > EPSF;
    r.x = bx ? 1.0f / (d.x + EPSF) : 0.0f;  hf.x = bx ? 0.0f : 1.0f;
    r.y = by ? 1.0f / (d.y + EPSF) : 0.0f;  hf.y = by ? 0.0f : 1.0f;
    r.z = bz ? 1.0f / (d.z + EPSF) : 0.0f;  hf.z = bz ? 0.0f : 1.0f;
    r.w = bw ? 1.0f / (d.w + EPSF) : 0.0f;  hf.w = bw ? 0.0f : 1.0f;

    int p0  = q * 4;
    int b   = p0 >> 18;
    int pix = p0 & (HWn - 1);

    const uint4* A4 = reinterpret_cast<const uint4*>(g_Ah);
    uint4 u[4][2];
#pragma unroll
    for (int t = 0; t < 4; t++) {
        u[t][0] = A4[(size_t)(p0 + t) * 2 + 0];   // channels 0..7
        u[t][1] = A4[(size_t)(p0 + t) * 2 + 1];   // channels 8..15
    }

    float4* ob = out4 + ((size_t)b * Cn * HWn + pix) / 4;

#pragma unroll
    for (int g = 0; g < 4; g++) {
        float2 lo[4], hi[4];
#pragma unroll
        for (int t = 0; t < 4; t++) {
            const uint32_t* w32 = reinterpret_cast<const uint32_t*>(&u[t][g >> 1]);
            uint32_t wlo = w32[(g & 1) * 2 + 0];
            uint32_t whi = w32[(g & 1) * 2 + 1];
            lo[t] = __half22float2(*reinterpret_cast<const __half2*>(&wlo));
            hi[t] = __half22float2(*reinterpret_cast<const __half2*>(&whi));
        }

        float4 v0 = make_float4(fmaf(lo[0].x, r.x, hf.x), fmaf(lo[1].x, r.y, hf.y),
                                fmaf(lo[2].x, r.z, hf.z), fmaf(lo[3].x, r.w, hf.w));
        float4 v1 = make_float4(fmaf(lo[0].y, r.x, hf.x), fmaf(lo[1].y, r.y, hf.y),
                                fmaf(lo[2].y, r.z, hf.z), fmaf(lo[3].y, r.w, hf.w));
        float4 v2 = make_float4(fmaf(hi[0].x, r.x, hf.x), fmaf(hi[1].x, r.y, hf.y),
                                fmaf(hi[2].x, r.z, hf.z), fmaf(hi[3].x, r.w, hf.w));
        float4 v3 = make_float4(fmaf(hi[0].y, r.x, hf.x), fmaf(hi[1].y, r.y, hf.y),
                                fmaf(hi[2].y, r.z, hf.z), fmaf(hi[3].y, r.w, hf.w));

        ob[(size_t)(4 * g + 0) * (HWn / 4)] = v0;
        ob[(size_t)(4 * g + 1) * (HWn / 4)] = v1;
        ob[(size_t)(4 * g + 2) * (HWn / 4)] = v2;
        ob[(size_t)(4 * g + 3) * (HWn / 4)] = v3;
    }
}

// ---------------------------------------------------------------------------
extern "C" void kernel_launch(void* const* d_in, const int* in_sizes, int n_in,
                              void* d_out, int out_size) {
    const float* x    = (const float*)d_in[0];
    const float* grid = (const float*)d_in[1];
    float*       out  = (float*)d_out;

    {
        int total = (NOUT * 2) / 16 + NPIX / 4;
        zero_kernel<<<(total + 255) / 256, 256>>>();
    }
    scatter_kernel<<<NPIX / 256, 256>>>(x, grid);
    normalize_kernel<<<(NPIX / 4 + 255) / 256, 256>>>((float4*)out);
}

// round 8
// speedup vs baseline: 2.3783x; 1.0443x over previous
#include <cuda_runtime.h>
#include <cuda_fp16.h>
#include <cstdint>

#define Bn 4
#define Cn 16
#define Hn 512
#define Wn 512
#define HWn (Hn*Wn)        // 262144
#define NPIX (Bn*HWn)      // 1048576
#define NOUT (Bn*Cn*HWn)   // 16777216
#define EPSF 1e-10f

// Channel-contiguous f16 accumulator A': [pixel][16 x half] = 32B/record. 32 MB.
__device__ __half2 g_Ah[NOUT / 2];
// Weight-sum accumulator D (B,H,W), f32 for exact hole detection. 4 MB.
__device__ float g_D[NPIX];

// ---------------------------------------------------------------------------
// Kernel 1: zero scratch A' and D.
// ---------------------------------------------------------------------------
__global__ void zero_kernel() {
    const int n_a4 = (NOUT * 2) / 16;   // 2097152 float4-units of A (32MB)
    const int n_d4 = NPIX / 4;          // 262144
    int idx = blockIdx.x * blockDim.x + threadIdx.x;
    float4 z = make_float4(0.f, 0.f, 0.f, 0.f);
    if (idx < n_a4) {
        reinterpret_cast<float4*>(g_Ah)[idx] = z;
    } else if (idx < n_a4 + n_d4) {
        reinterpret_cast<float4*>(g_D)[idx - n_a4] = z;
    }
}

// ---------------------------------------------------------------------------
// f16 corner emission: 8 HMUL2 -> 2 x 16B v4.f16x2 RED messages (ISA max).
// ---------------------------------------------------------------------------
__device__ __forceinline__ void emit_corner_h(bool v, __half2* base, float w,
                                              const uint32_t* xh) {
    if (!v) return;
    __half2 wh = __float2half2_rn(w);
    uint32_t m[8];
#pragma unroll
    for (int k = 0; k < 8; k++) {
        __half2 prod = __hmul2(*reinterpret_cast<const __half2*>(&xh[k]), wh);
        m[k] = *reinterpret_cast<uint32_t*>(&prod);
    }
    asm volatile("red.global.add.noftz.v4.f16x2 [%0], {%1,%2,%3,%4};"
                 :: "l"(base), "r"(m[0]), "r"(m[1]), "r"(m[2]), "r"(m[3]) : "memory");
    asm volatile("red.global.add.noftz.v4.f16x2 [%0], {%1,%2,%3,%4};"
                 :: "l"(base + 4), "r"(m[4]), "r"(m[5]), "r"(m[6]), "r"(m[7]) : "memory");
}

__device__ __forceinline__ void red4(float* addr, float a, float b, float c, float d) {
    asm volatile("red.global.add.v4.f32 [%0], {%1,%2,%3,%4};"
                 :: "l"(addr), "f"(a), "f"(b), "f"(c), "f"(d) : "memory");
}

// D row emission: cells (oa, oa+1) in one row. If both fit in a 16B quad
// (oa%4 != 3), emit ONE zero-padded v4 RED (+0.0f adds are exact no-ops).
__device__ __forceinline__ void emit_D_row(float* Db, bool va, bool vb,
                                           int oa, float wa, float wb) {
    if (!(va || vb)) return;
    int pos = oa & 3;
    if (pos < 3) {
        float vals[4] = {0.f, 0.f, 0.f, 0.f};
        if (va) vals[pos] = wa;
        if (vb) vals[pos + 1] = wb;
        red4(Db + (oa & ~3), vals[0], vals[1], vals[2], vals[3]);
    } else {
        if (va) atomicAdd(Db + oa, wa);
        if (vb) atomicAdd(Db + oa + 1, wb);
    }
}

// ---------------------------------------------------------------------------
// Kernel 2: scatter. One thread per source pixel.
// 8 x 16B A-messages + ~2.5 D-messages = ~10.5 LSU lane-messages per pixel.
// ---------------------------------------------------------------------------
__global__ void scatter_kernel(const float* __restrict__ x,
                               const float* __restrict__ grid) {
    int p = blockIdx.x * blockDim.x + threadIdx.x;
    if (p >= NPIX) return;

    float2 gv = __ldcs(reinterpret_cast<const float2*>(grid) + p);

    float g0 = (gv.x + 1.0f) * 0.5f;
    float g1 = (gv.y + 1.0f) * 0.5f;
    float gi = fminf(fmaxf(fmaf(g0, 512.0f, 1.0f), 0.0f), 513.0f);
    float gj = fminf(fmaxf(fmaf(g1, 512.0f, 1.0f), 0.0f), 513.0f);

    int ii0 = (int)gi;
    int jj0 = (int)gj;
    float fi = gi - (float)ii0;
    float fj = gj - (float)jj0;
    float wi0 = 1.0f - fi, wi1 = fi;
    float wj0 = 1.0f - fj, wj1 = fj;

    int oi0 = ii0 - 1, oi1 = ii0;
    int oj0 = jj0 - 1, oj1 = jj0;
    bool vi0 = (unsigned)oi0 < (unsigned)Hn;
    bool vi1 = (unsigned)oi1 < (unsigned)Hn;
    bool vj0 = (unsigned)oj0 < (unsigned)Wn;
    bool vj1 = (unsigned)oj1 < (unsigned)Wn;

    bool  v00 = vi0 && vj0,       v01 = vi0 && vj1;
    bool  v10 = vi1 && vj0,       v11 = vi1 && vj1;
    int   o00 = oi0 * Wn + oj0,   o01 = oi0 * Wn + oj1;
    int   o10 = oi1 * Wn + oj0,   o11 = oi1 * Wn + oj1;
    float w00 = wi0 * wj0,        w01 = wi0 * wj1;
    float w10 = wi1 * wj0,        w11 = wi1 * wj1;

    int b   = p >> 18;
    int pix = p & (HWn - 1);

    // D accumulation with pad-to-quad packing
    float* Db = g_D + b * HWn;
    if (vi0) emit_D_row(Db, vj0, vj1, o00, w00, w01);
    if (vi1) emit_D_row(Db, vj0, vj1, o10, w10, w11);

    // Load the 16 channel values (streaming) and convert to f16x2 ONCE.
    const float* xp = x + (size_t)b * Cn * HWn + pix;
    float xv[16];
#pragma unroll
    for (int c = 0; c < Cn; c++) xv[c] = __ldcs(xp + c * HWn);
    uint32_t xh[8];
#pragma unroll
    for (int k = 0; k < 8; k++) {
        __half2 h = __floats2half2_rn(xv[2 * k], xv[2 * k + 1]);
        xh[k] = *reinterpret_cast<uint32_t*>(&h);
    }

    // Scatter into f16 channel-contiguous scratch: 2 x 16B RED per corner
    __half2* Ab = g_Ah + (size_t)b * HWn * 8;   // 8 half2 per pixel record
    emit_corner_h(v00, Ab + (size_t)o00 * 8, w00, xh);
    emit_corner_h(v01, Ab + (size_t)o01 * 8, w01, xh);
    emit_corner_h(v10, Ab + (size_t)o10 * 8, w10, xh);
    emit_corner_h(v11, Ab + (size_t)o11 * 8, w11, xh);
}

// ---------------------------------------------------------------------------
// Kernel 3: normalize + transpose [pix][c](f16) -> [c][pix](f32).
// 4x parallel: one thread per (pixel-quad, channel-group). 1M threads.
// ---------------------------------------------------------------------------
__global__ void normalize_kernel(float4* __restrict__ out4) {
    int t = blockIdx.x * blockDim.x + threadIdx.x;
    if (t >= NPIX) return;
    int q = t >> 2;      // pixel quad id
    int g = t & 3;       // channel group (channels 4g..4g+3)

    float4 d = reinterpret_cast<const float4*>(g_D)[q];
    float4 r, hf;
    bool bx = d.x > EPSF, by = d.y > EPSF, bz = d.z > EPSF, bw = d.w > EPSF;
    r.x = bx ? 1.0f / (d.x + EPSF) : 0.0f;  hf.x = bx ? 0.0f : 1.0f;
    r.y = by ? 1.0f / (d.y + EPSF) : 0.0f;  hf.y = by ? 0.0f : 1.0f;
    r.z = bz ? 1.0f / (d.z + EPSF) : 0.0f;  hf.z = bz ? 0.0f : 1.0f;
    r.w = bw ? 1.0f / (d.w + EPSF) : 0.0f;  hf.w = bw ? 0.0f : 1.0f;

    int p0  = q * 4;
    int b   = p0 >> 18;
    int pix = p0 & (HWn - 1);

    // Pixel record = 32B = 4 uint2 groups; this thread reads group g of 4 pixels.
    const uint2* A2 = reinterpret_cast<const uint2*>(g_Ah);
    uint2 u0 = A2[(size_t)(p0 + 0) * 4 + g];
    uint2 u1 = A2[(size_t)(p0 + 1) * 4 + g];
    uint2 u2 = A2[(size_t)(p0 + 2) * 4 + g];
    uint2 u3 = A2[(size_t)(p0 + 3) * 4 + g];

    float2 lo0 = __half22float2(*reinterpret_cast<const __half2*>(&u0.x));
    float2 hi0 = __half22float2(*reinterpret_cast<const __half2*>(&u0.y));
    float2 lo1 = __half22float2(*reinterpret_cast<const __half2*>(&u1.x));
    float2 hi1 = __half22float2(*reinterpret_cast<const __half2*>(&u1.y));
    float2 lo2 = __half22float2(*reinterpret_cast<const __half2*>(&u2.x));
    float2 hi2 = __half22float2(*reinterpret_cast<const __half2*>(&u2.y));
    float2 lo3 = __half22float2(*reinterpret_cast<const __half2*>(&u3.x));
    float2 hi3 = __half22float2(*reinterpret_cast<const __half2*>(&u3.y));

    float4 v0 = make_float4(fmaf(lo0.x, r.x, hf.x), fmaf(lo1.x, r.y, hf.y),
                            fmaf(lo2.x, r.z, hf.z), fmaf(lo3.x, r.w, hf.w));
    float4 v1 = make_float4(fmaf(lo0.y, r.x, hf.x), fmaf(lo1.y, r.y, hf.y),
                            fmaf(lo2.y, r.z, hf.z), fmaf(lo3.y, r.w, hf.w));
    float4 v2 = make_float4(fmaf(hi0.x, r.x, hf.x), fmaf(hi1.x, r.y, hf.y),
                            fmaf(hi2.x, r.z, hf.z), fmaf(hi3.x, r.w, hf.w));
    float4 v3 = make_float4(fmaf(hi0.y, r.x, hf.x), fmaf(hi1.y, r.y, hf.y),
                            fmaf(hi2.y, r.z, hf.z), fmaf(hi3.y, r.w, hf.w));

    float4* ob = out4 + ((size_t)b * Cn * HWn + pix) / 4;
    ob[(size_t)(4 * g + 0) * (HWn / 4)] = v0;
    ob[(size_t)(4 * g + 1) * (HWn / 4)] = v1;
    ob[(size_t)(4 * g + 2) * (HWn / 4)] = v2;
    ob[(size_t)(4 * g + 3) * (HWn / 4)] = v3;
}

// ---------------------------------------------------------------------------
extern "C" void kernel_launch(void* const* d_in, const int* in_sizes, int n_in,
                              void* d_out, int out_size) {
    const float* x    = (const float*)d_in[0];
    const float* grid = (const float*)d_in[1];
    float*       out  = (float*)d_out;

    {
        int total = (NOUT * 2) / 16 + NPIX / 4;
        zero_kernel<<<(total + 255) / 256, 256>>>();
    }
    scatter_kernel<<<NPIX / 256, 256>>>(x, grid);
    normalize_kernel<<<NPIX / 256, 256>>>((float4*)out);
}